// round 14
// baseline (speedup 1.0000x reference)
#include <cuda_runtime.h>
#include <math_constants.h>

// Static shape: N=65536, 16 segments of SEG=4096, D=3, K=20.
// T=2 split: each query is handled by 2 threads (halves of the candidate
// range), doubling warp-level parallelism (we were grid-limited at 13.8
// warps/SM; register ceiling is ~27 warps/SM, which T=2 exactly reaches).
#define KNN 20
#define NPTS 65536
#define SEG 4096
#define HALF 2048
#define QPB 64           // queries per block
#define BLOCK 128        // QPB * 2 threads
#define BUFCAP 16
#define NPH 12

typedef unsigned long long u64;

__device__ __forceinline__ u64 pk2(float lo, float hi) {
    u64 r;
    asm("mov.b64 %0, {%1, %2};" : "=l"(r) : "f"(lo), "f"(hi));
    return r;
}
__device__ __forceinline__ void upk2(float& lo, float& hi, u64 v) {
    asm("mov.b64 {%0, %1}, %2;" : "=f"(lo), "=f"(hi) : "l"(v));
}
__device__ __forceinline__ u64 add2(u64 a, u64 b) {
    u64 r;
    asm("add.rn.f32x2 %0, %1, %2;" : "=l"(r) : "l"(a), "l"(b));
    return r;
}
__device__ __forceinline__ u64 mul2(u64 a, u64 b) {
    u64 r;
    asm("mul.rn.f32x2 %0, %1, %2;" : "=l"(r) : "l"(a), "l"(b));
    return r;
}
__device__ __forceinline__ u64 fma2(u64 a, u64 b, u64 c) {
    u64 r;
    asm("fma.rn.f32x2 %0, %1, %2, %3;" : "=l"(r) : "l"(a), "l"(b), "l"(c));
    return r;
}

// Parallel predicated-shift insert into sorted ascending top-K.
// Strict '<' + ascending-j visit order = lax.top_k tie-breaking.
__device__ __forceinline__ void par_insert(float d, int j, float* dist,
                                           int* idx) {
    if (d < dist[KNN - 1]) {
        bool c[KNN];
#pragma unroll
        for (int k = 0; k < KNN; ++k) c[k] = d < dist[k];
#pragma unroll
        for (int k = KNN - 1; k > 0; --k) {
            dist[k] = c[k - 1] ? dist[k - 1] : (c[k] ? d : dist[k]);
            idx[k] = c[k - 1] ? idx[k - 1] : (c[k] ? j : idx[k]);
        }
        if (c[0]) {
            dist[0] = d;
            idx[0] = j;
        }
    }
}

__global__ __launch_bounds__(BLOCK, 7) void knn_kernel(
    const float* __restrict__ x, float* __restrict__ out) {
    // Scan phase: per-thread push buffer, buf[k*BLOCK + tid], k < BUFCAP.
    // Merge phase (after final __syncthreads): per-thread sorted list,
    // buf[tid*KNN + k], k < KNN  (BLOCK*KNN = 2560 entries = 20 KB).
    __shared__ float2 buf[BLOCK * KNN];

    const int tid = threadIdx.x;
    const int q = tid & (QPB - 1);         // query slot in block
    const int half = tid >> 6;             // 0: j in [0,2048), 1: [2048,4096)
    const int blocksPerSeg = SEG / QPB;    // 64
    const int seg = blockIdx.x / blocksPerSeg;
    const int base = seg * SEG;
    const int qg = base + (blockIdx.x % blocksPerSeg) * QPB + q;
    const int hbase = half * HALF;

    // Key: d_j = xj*(xj+m2x)+yj*(yj+m2y)+zj*(zj+m2z) = |pj|^2 - 2 q.pj
    const float m2x = -2.0f * x[qg * 3 + 0];
    const float m2y = -2.0f * x[qg * 3 + 1];
    const float m2z = -2.0f * x[qg * 3 + 2];
    const u64 m2x2 = pk2(m2x, m2x);
    const u64 m2y2 = pk2(m2y, m2y);
    const u64 m2z2 = pk2(m2z, m2z);

    float dist[KNN];
    int idx[KNN];
#pragma unroll
    for (int k = 0; k < KNN; ++k) {
        dist[k] = CUDART_INF_F;
        idx[k] = 0;
    }

    float thr = CUDART_INF_F;
    int cnt = 0;

    // Candidate data: warp-uniform LDG.128 (3 x float4 = 4 points), L1/L2-hot
    // (whole input is 768 KB, L2-resident; per-segment 48 KB mostly L1-hot).
    const float4* __restrict__ xv =
        (const float4*)(x + (size_t)(base + hbase) * 3);

#define PUSH(dv, jv)                                                         \
    do {                                                                     \
        if ((dv) < thr) {                                                    \
            if (cnt < BUFCAP) {                                              \
                buf[cnt * BLOCK + tid] =                                     \
                    make_float2((dv), __int_as_float(jv));                   \
                cnt++;                                                       \
            } else {                                                         \
                par_insert((dv), (jv), dist, idx);                           \
            }                                                                \
        }                                                                    \
    } while (0)

    // Doubling drain schedule over the 2048-candidate sub-scan.
    constexpr int B[NPH + 1] = {0,   20,  32,  48,  72,   108, 164,
                                248, 372, 560, 840, 1260, 2048};

#pragma unroll
    for (int ph = 0; ph < NPH; ++ph) {
#pragma unroll 2
        for (int r4 = B[ph] / 4; r4 < B[ph + 1] / 4; ++r4) {
            float4 a = xv[3 * r4 + 0];
            float4 b = xv[3 * r4 + 1];
            float4 c = xv[3 * r4 + 2];
            const int j = hbase + r4 * 4;

            u64 vx01 = pk2(a.x, a.w), vy01 = pk2(a.y, b.x), vz01 = pk2(a.z, b.y);
            u64 vx23 = pk2(b.z, c.y), vy23 = pk2(b.w, c.z), vz23 = pk2(c.x, c.w);

            u64 acc01 = mul2(vx01, add2(vx01, m2x2));
            acc01 = fma2(vy01, add2(vy01, m2y2), acc01);
            acc01 = fma2(vz01, add2(vz01, m2z2), acc01);
            u64 acc23 = mul2(vx23, add2(vx23, m2x2));
            acc23 = fma2(vy23, add2(vy23, m2y2), acc23);
            acc23 = fma2(vz23, add2(vz23, m2z2), acc23);

            float d0, d1, d2, d3;
            upk2(d0, d1, acc01);
            upk2(d2, d3, acc23);

            PUSH(d0, j + 0);
            PUSH(d1, j + 1);
            PUSH(d2, j + 2);
            PUSH(d3, j + 3);
        }

        // Drain buffered items in push (= ascending j) order.
        int mx = __reduce_max_sync(0xffffffffu, cnt);
        for (int t = 0; t < mx; ++t) {
            if (t < cnt) {
                float2 en = buf[t * BLOCK + tid];
                par_insert(en.x, __float_as_int(en.y), dist, idx);
            }
        }
        cnt = 0;
        thr = dist[KNN - 1];
    }
#undef PUSH

    // ---- merge the two halves of each query ----
    __syncthreads();  // everyone done with the push buffer
#pragma unroll
    for (int k = 0; k < KNN; ++k)
        buf[tid * KNN + k] = make_float2(dist[k], __int_as_float(idx[k]));
    __syncthreads();

    if (half == 0) {
        // Merge my list (j < 2048) with partner's (j >= 2048). On equal d,
        // half-0 wins (strictly lower j) -> comparator da <= db.
        const float2* la = &buf[tid * KNN];
        const float2* lb = &buf[(tid + QPB) * KNN];
        int ia = 0, ib = 0;
        float* o = out + (size_t)qg * KNN;
#pragma unroll
        for (int k = 0; k < KNN; ++k) {
            float2 ea = la[ia], eb = lb[ib];
            bool ta = ea.x <= eb.x;
            o[k] = (float)(base + __float_as_int(ta ? ea.y : eb.y));
            ia += ta;
            ib += !ta;
        }
    }
}

extern "C" void kernel_launch(void* const* d_in, const int* in_sizes, int n_in,
                              void* d_out, int out_size) {
    // x is the larger input under both elements and bytes conventions.
    int xi = 0;
    for (int i = 1; i < n_in; ++i)
        if (in_sizes[i] > in_sizes[xi]) xi = i;
    const float* x = (const float*)d_in[xi];
    float* out = (float*)d_out;

    dim3 grid(NPTS / QPB);  // 1024 blocks x 128 threads, ~7 blocks/SM
    knn_kernel<<<grid, BLOCK>>>(x, out);
}